// round 5
// baseline (speedup 1.0000x reference)
#include <cuda_runtime.h>
#include <cuda_bf16.h>
#include <cstdint>

#define NODES 40000
#define EDGES 640000
#define DIM 128
#define GRAPHS 512
#define NEG_SLOPE 0.2f
#define BN_EPS 1e-5f

// ---------------- scratch (no allocations allowed) ----------------
__device__ float d_h0[NODES * DIM];
__device__ float d_xl[NODES * DIM];
__device__ float d_xr[NODES * DIM];
__device__ __nv_bfloat16 d_hhi[NODES * DIM];
__device__ __nv_bfloat16 d_hlo[NODES * DIM];
__device__ __nv_bfloat16 d_whi[3 * 2 * DIM * DIM];
__device__ __nv_bfloat16 d_wlo[3 * 2 * DIM * DIM];
__device__ int d_deg[NODES];
__device__ int d_rowptr[NODES + 1];
__device__ int d_cursor[NODES];
__device__ int d_srcs[EDGES];

__device__ __forceinline__ uint32_t smem_u32(const void* p) {
    uint32_t a;
    asm("{ .reg .u64 t; cvta.to.shared.u64 t, %1; cvt.u32.u64 %0, t; }" : "=r"(a) : "l"(p));
    return a;
}
__device__ __forceinline__ void ldsm_x4(uint32_t* r, uint32_t addr) {
    asm volatile("ldmatrix.sync.aligned.m8n8.x4.shared.b16 {%0,%1,%2,%3}, [%4];"
                 : "=r"(r[0]), "=r"(r[1]), "=r"(r[2]), "=r"(r[3]) : "r"(addr));
}
__device__ __forceinline__ void ldsm_x4_t(uint32_t* r, uint32_t addr) {
    asm volatile("ldmatrix.sync.aligned.m8n8.x4.trans.shared.b16 {%0,%1,%2,%3}, [%4];"
                 : "=r"(r[0]), "=r"(r[1]), "=r"(r[2]), "=r"(r[3]) : "r"(addr));
}
__device__ __forceinline__ void mma16816(float* c, const uint32_t* a, const uint32_t* b) {
    asm volatile(
        "mma.sync.aligned.m16n8k16.row.col.f32.bf16.bf16.f32 "
        "{%0,%1,%2,%3}, {%4,%5,%6,%7}, {%8,%9}, {%0,%1,%2,%3};"
        : "+f"(c[0]), "+f"(c[1]), "+f"(c[2]), "+f"(c[3])
        : "r"(a[0]), "r"(a[1]), "r"(a[2]), "r"(a[3]), "r"(b[0]), "r"(b[1]));
}

// ---------------- CSR build ----------------
__global__ void k_zero_deg() {
    int i = blockIdx.x * blockDim.x + threadIdx.x;
    if (i < NODES) d_deg[i] = 0;
}
__global__ void k_hist(const int* __restrict__ ei) {
    int e = blockIdx.x * blockDim.x + threadIdx.x;
    if (e < EDGES) atomicAdd(&d_deg[ei[EDGES + e]], 1);
}
#define SCAN_CH 40
__global__ void k_scan() {
    __shared__ int ws[32];
    int t = threadIdx.x, lane = t & 31, wid = t >> 5;
    int base = t * SCAN_CH;
    int s = 0;
    #pragma unroll 4
    for (int k = 0; k < SCAN_CH; k++) {
        int idx = base + k;
        if (idx < NODES) s += d_deg[idx];
    }
    int x = s;
    #pragma unroll
    for (int o = 1; o < 32; o <<= 1) {
        int y = __shfl_up_sync(0xffffffffu, x, o);
        if (lane >= o) x += y;
    }
    if (lane == 31) ws[wid] = x;
    __syncthreads();
    if (wid == 0) {
        int sv = ws[lane], sx = sv;
        #pragma unroll
        for (int o = 1; o < 32; o <<= 1) {
            int y = __shfl_up_sync(0xffffffffu, sx, o);
            if (lane >= o) sx += y;
        }
        ws[lane] = sx - sv;
    }
    __syncthreads();
    int run = ws[wid] + x - s;
    #pragma unroll 4
    for (int k = 0; k < SCAN_CH; k++) {
        int idx = base + k;
        if (idx < NODES) {
            int dg = d_deg[idx];
            d_rowptr[idx] = run;
            d_cursor[idx] = run;
            run += dg;
        }
    }
    if (t == 1023) d_rowptr[NODES] = run;
}
__global__ void k_scatter(const int* __restrict__ ei) {
    int e = blockIdx.x * blockDim.x + threadIdx.x;
    if (e < EDGES) {
        int dst = ei[EDGES + e];
        int pos = atomicAdd(&d_cursor[dst], 1);
        d_srcs[pos] = ei[e];
    }
}

// ---------------- fp32 -> bf16 hi/lo converts ----------------
__global__ void k_convert_x(const float* __restrict__ x) {
    int i = blockIdx.x * blockDim.x + threadIdx.x;
    if (i < NODES * DIM) {
        float v = x[i];
        __nv_bfloat16 h = __float2bfloat16(v);
        d_hhi[i] = h;
        d_hlo[i] = __float2bfloat16(v - __bfloat162float(h));
    }
}
__global__ void k_convert_w(const float* __restrict__ Wl, const float* __restrict__ Wr) {
    int l = blockIdx.x >> 1, m = blockIdx.x & 1;
    const float* W = (m ? Wr : Wl) + (size_t)l * DIM * DIM;
    __nv_bfloat16* oh = d_whi + (size_t)(l * 2 + m) * DIM * DIM;
    __nv_bfloat16* ol = d_wlo + (size_t)(l * 2 + m) * DIM * DIM;
    for (int t = threadIdx.x; t < DIM * DIM; t += blockDim.x) {
        float v = W[t];
        __nv_bfloat16 h = __float2bfloat16(v);
        oh[t] = h;
        ol[t] = __float2bfloat16(v - __bfloat162float(h));
    }
}

// ---------------- HMMA dual GEMM (bf16x3 emulated fp32) ----------------
#define SA_HI 0
#define SA_LO 32768
#define SW_HI 65536
#define SW_LO 98304
#define GSMEM 131072

__global__ __launch_bounds__(256, 1) void k_gemm_tc(
    const __nv_bfloat16* __restrict__ Ahi, const __nv_bfloat16* __restrict__ Alo,
    const __nv_bfloat16* __restrict__ Whi, const __nv_bfloat16* __restrict__ Wlo,
    const float* __restrict__ bl, const float* __restrict__ br)
{
    extern __shared__ char smem[];
    uint32_t sb = smem_u32(smem);
    int tid = threadIdx.x;
    int row0 = blockIdx.x * 128;
    int mat = blockIdx.y;

    const float* bias = mat ? br : bl;
    float* out = mat ? d_xr : d_xl;
    const uint4* ahi4 = (const uint4*)Ahi;
    const uint4* alo4 = (const uint4*)Alo;
    const uint4* wh4 = (const uint4*)(Whi + (size_t)mat * DIM * DIM);
    const uint4* wl4 = (const uint4*)(Wlo + (size_t)mat * DIM * DIM);

    for (int t = tid; t < 2048; t += 256) {
        int r = t >> 4, c = t & 15;
        int so = r * 256 + (((c ^ (r & 7))) << 4);
        int grow = row0 + r;
        if (grow > NODES - 1) grow = NODES - 1;
        *(uint4*)(smem + SA_HI + so) = ahi4[grow * 16 + c];
        *(uint4*)(smem + SA_LO + so) = alo4[grow * 16 + c];
        *(uint4*)(smem + SW_HI + so) = wh4[t];
        *(uint4*)(smem + SW_LO + so) = wl4[t];
    }
    __syncthreads();

    int w = tid >> 5, lane = tid & 31;
    int mBase = (w >> 2) * 64;
    int nBase = (w & 3) * 32;

    float acc[4][4][4];
    #pragma unroll
    for (int mt = 0; mt < 4; mt++)
        #pragma unroll
        for (int nt = 0; nt < 4; nt++)
            #pragma unroll
            for (int j = 0; j < 4; j++) acc[mt][nt][j] = 0.f;

    int arow = lane & 15;
    int asel = lane >> 4;
    int brow_in = (lane & 7) + ((lane >> 3) & 1) * 8;
    int bsel = lane >> 4;

    #pragma unroll
    for (int ks = 0; ks < 8; ks++) {
        uint32_t ah[4][4], al[4][4];
        int achunk = ks * 2 + asel;
        #pragma unroll
        for (int mt = 0; mt < 4; mt++) {
            int r = mBase + mt * 16 + arow;
            uint32_t off = r * 256 + ((achunk ^ (r & 7)) << 4);
            ldsm_x4(ah[mt], sb + SA_HI + off);
            ldsm_x4(al[mt], sb + SA_LO + off);
        }
        uint32_t bh[2][4], bo[2][4];
        int brow = ks * 16 + brow_in;
        #pragma unroll
        for (int nt2 = 0; nt2 < 2; nt2++) {
            int chunk = ((nBase + nt2 * 16) >> 3) + bsel;
            uint32_t off = brow * 256 + ((chunk ^ (brow & 7)) << 4);
            ldsm_x4_t(bh[nt2], sb + SW_HI + off);
            ldsm_x4_t(bo[nt2], sb + SW_LO + off);
        }
        #pragma unroll
        for (int mt = 0; mt < 4; mt++)
            #pragma unroll
            for (int nt = 0; nt < 4; nt++) {
                const uint32_t* ph = &bh[nt >> 1][(nt & 1) * 2];
                const uint32_t* pl = &bo[nt >> 1][(nt & 1) * 2];
                mma16816(acc[mt][nt], ah[mt], ph);
                mma16816(acc[mt][nt], al[mt], ph);
                mma16816(acc[mt][nt], ah[mt], pl);
            }
    }

    int r0 = lane >> 2;
    int c2 = (lane & 3) * 2;
    #pragma unroll
    for (int nt = 0; nt < 4; nt++) {
        int col = nBase + nt * 8 + c2;
        float2 bi = *(const float2*)(bias + col);
        #pragma unroll
        for (int mt = 0; mt < 4; mt++) {
            int g0 = row0 + mBase + mt * 16 + r0;
            if (g0 < NODES) {
                float2 o = {acc[mt][nt][0] + bi.x, acc[mt][nt][1] + bi.y};
                *(float2*)(out + (size_t)g0 * DIM + col) = o;
            }
            int g1 = g0 + 8;
            if (g1 < NODES) {
                float2 o = {acc[mt][nt][2] + bi.x, acc[mt][nt][3] + bi.y};
                *(float2*)(out + (size_t)g1 * DIM + col) = o;
            }
        }
    }
}

// ---------------- GATv2 aggregation: half-warp per edge ----------------
// lane = h16*16 + s ; lane owns channel octet [8s, 8s+8); head = s>>2.
__device__ __forceinline__ float leaky_dot(float4 v, float4 x, float4 w) {
    float ax = v.x + x.x, ay = v.y + x.y, az = v.z + x.z, aw = v.w + x.w;
    ax = ax > 0.f ? ax : NEG_SLOPE * ax;
    ay = ay > 0.f ? ay : NEG_SLOPE * ay;
    az = az > 0.f ? az : NEG_SLOPE * az;
    aw = aw > 0.f ? aw : NEG_SLOPE * aw;
    return ax * w.x + ay * w.y + az * w.z + aw * w.w;
}

__global__ __launch_bounds__(256) void k_gat(
    const float* __restrict__ xl, const float* __restrict__ xr,
    const float* __restrict__ att, const float* __restrict__ conv_bias,
    const float* __restrict__ bn_gamma, const float* __restrict__ bn_beta,
    const float* __restrict__ bn_mean, const float* __restrict__ bn_var,
    float* __restrict__ hout, int write_bf, int write_f32)
{
    int i = blockIdx.x * 8 + (threadIdx.x >> 5);
    if (i >= NODES) return;
    int lane = threadIdx.x & 31;
    int h16 = lane >> 4;
    int s = lane & 15;
    int c = s * 8;

    float4 w0  = *(const float4*)(att + c);
    float4 w1  = *(const float4*)(att + c + 4);
    float4 xr0 = *(const float4*)(xr + (size_t)i * DIM + c);
    float4 xr1 = *(const float4*)(xr + (size_t)i * DIM + c + 4);

    // self loop (both halves compute identical m0; only half 0 seeds acc/denom)
    float4 sv0 = *(const float4*)(xl + (size_t)i * DIM + c);
    float4 sv1 = *(const float4*)(xl + (size_t)i * DIM + c + 4);
    float p = leaky_dot(sv0, xr0, w0) + leaky_dot(sv1, xr1, w1);
    p += __shfl_xor_sync(0xffffffffu, p, 1);
    p += __shfl_xor_sync(0xffffffffu, p, 2);
    float m0 = p;

    float denom;
    float4 acc0, acc1;
    if (h16 == 0) {
        denom = 1.0f;
        acc0 = sv0; acc1 = sv1;
    } else {
        denom = 0.0f;
        acc0 = make_float4(0.f, 0.f, 0.f, 0.f);
        acc1 = make_float4(0.f, 0.f, 0.f, 0.f);
    }

    int beg = d_rowptr[i];
    int end = d_rowptr[i + 1];
    #pragma unroll 2
    for (int j = beg; j < end; j += 2) {
        int jj = j + h16;
        bool act = jj < end;
        int src = __ldg(&d_srcs[act ? jj : j]);
        const float4* vp = (const float4*)(xl + (size_t)src * DIM + c);
        float4 v0 = __ldg(vp);
        float4 v1 = __ldg(vp + 1);
        float d = leaky_dot(v0, xr0, w0) + leaky_dot(v1, xr1, w1);
        d += __shfl_xor_sync(0xffffffffu, d, 1);
        d += __shfl_xor_sync(0xffffffffu, d, 2);
        float a = act ? __expf(d - m0) : 0.f;
        denom += a;
        acc0.x = fmaf(a, v0.x, acc0.x);
        acc0.y = fmaf(a, v0.y, acc0.y);
        acc0.z = fmaf(a, v0.z, acc0.z);
        acc0.w = fmaf(a, v0.w, acc0.w);
        acc1.x = fmaf(a, v1.x, acc1.x);
        acc1.y = fmaf(a, v1.y, acc1.y);
        acc1.z = fmaf(a, v1.z, acc1.z);
        acc1.w = fmaf(a, v1.w, acc1.w);
    }

    // combine halves (once per node)
    denom  += __shfl_xor_sync(0xffffffffu, denom, 16);
    acc0.x += __shfl_xor_sync(0xffffffffu, acc0.x, 16);
    acc0.y += __shfl_xor_sync(0xffffffffu, acc0.y, 16);
    acc0.z += __shfl_xor_sync(0xffffffffu, acc0.z, 16);
    acc0.w += __shfl_xor_sync(0xffffffffu, acc0.w, 16);
    acc1.x += __shfl_xor_sync(0xffffffffu, acc1.x, 16);
    acc1.y += __shfl_xor_sync(0xffffffffu, acc1.y, 16);
    acc1.z += __shfl_xor_sync(0xffffffffu, acc1.z, 16);
    acc1.w += __shfl_xor_sync(0xffffffffu, acc1.w, 16);

    if (h16 == 0) {
        float inv = 1.0f / denom;
        float4 bi0 = *(const float4*)(conv_bias + c);
        float4 bi1 = *(const float4*)(conv_bias + c + 4);
        float4 ga0 = *(const float4*)(bn_gamma + c);
        float4 ga1 = *(const float4*)(bn_gamma + c + 4);
        float4 be0 = *(const float4*)(bn_beta + c);
        float4 be1 = *(const float4*)(bn_beta + c + 4);
        float4 mu0 = *(const float4*)(bn_mean + c);
        float4 mu1 = *(const float4*)(bn_mean + c + 4);
        float4 va0 = *(const float4*)(bn_var + c);
        float4 va1 = *(const float4*)(bn_var + c + 4);
        float4 o0, o1;
        o0.x = fmaxf((acc0.x * inv + bi0.x - mu0.x) * rsqrtf(va0.x + BN_EPS) * ga0.x + be0.x, 0.f);
        o0.y = fmaxf((acc0.y * inv + bi0.y - mu0.y) * rsqrtf(va0.y + BN_EPS) * ga0.y + be0.y, 0.f);
        o0.z = fmaxf((acc0.z * inv + bi0.z - mu0.z) * rsqrtf(va0.z + BN_EPS) * ga0.z + be0.z, 0.f);
        o0.w = fmaxf((acc0.w * inv + bi0.w - mu0.w) * rsqrtf(va0.w + BN_EPS) * ga0.w + be0.w, 0.f);
        o1.x = fmaxf((acc1.x * inv + bi1.x - mu1.x) * rsqrtf(va1.x + BN_EPS) * ga1.x + be1.x, 0.f);
        o1.y = fmaxf((acc1.y * inv + bi1.y - mu1.y) * rsqrtf(va1.y + BN_EPS) * ga1.y + be1.y, 0.f);
        o1.z = fmaxf((acc1.z * inv + bi1.z - mu1.z) * rsqrtf(va1.z + BN_EPS) * ga1.z + be1.z, 0.f);
        o1.w = fmaxf((acc1.w * inv + bi1.w - mu1.w) * rsqrtf(va1.w + BN_EPS) * ga1.w + be1.w, 0.f);

        if (write_f32) {
            float4* hp = (float4*)(hout + (size_t)i * DIM + c);
            hp[0] = o0;
            hp[1] = o1;
        }
        if (write_bf) {
            __nv_bfloat16 h0x = __float2bfloat16(o0.x), h0y = __float2bfloat16(o0.y);
            __nv_bfloat16 h0z = __float2bfloat16(o0.z), h0w = __float2bfloat16(o0.w);
            __nv_bfloat16 h1x = __float2bfloat16(o1.x), h1y = __float2bfloat16(o1.y);
            __nv_bfloat16 h1z = __float2bfloat16(o1.z), h1w = __float2bfloat16(o1.w);
            __nv_bfloat162 hi[4] = {
                __nv_bfloat162(h0x, h0y), __nv_bfloat162(h0z, h0w),
                __nv_bfloat162(h1x, h1y), __nv_bfloat162(h1z, h1w)};
            *(uint4*)(d_hhi + (size_t)i * DIM + c) = *(uint4*)hi;
            __nv_bfloat162 lo[4] = {
                __nv_bfloat162(__float2bfloat16(o0.x - __bfloat162float(h0x)),
                               __float2bfloat16(o0.y - __bfloat162float(h0y))),
                __nv_bfloat162(__float2bfloat16(o0.z - __bfloat162float(h0z)),
                               __float2bfloat16(o0.w - __bfloat162float(h0w))),
                __nv_bfloat162(__float2bfloat16(o1.x - __bfloat162float(h1x)),
                               __float2bfloat16(o1.y - __bfloat162float(h1y))),
                __nv_bfloat162(__float2bfloat16(o1.z - __bfloat162float(h1z)),
                               __float2bfloat16(o1.w - __bfloat162float(h1w)))};
            *(uint4*)(d_hlo + (size_t)i * DIM + c) = *(uint4*)lo;
        }
    }
}

// ---------------- mean pool (batch sorted) + MLP 128->64->2 ----------------
__global__ void k_pool_mlp(
    const float* __restrict__ h, const int* __restrict__ batch,
    const float* __restrict__ W1, const float* __restrict__ b1,
    const float* __restrict__ W2, const float* __restrict__ b2,
    float* __restrict__ out)
{
    __shared__ float p[DIM];
    __shared__ float hid[64];
    int g = blockIdx.x;
    int t = threadIdx.x;

    int lo = 0, hi = NODES;
    while (lo < hi) { int mid = (lo + hi) >> 1; if (batch[mid] < g) lo = mid + 1; else hi = mid; }
    int beg = lo;
    hi = NODES;
    while (lo < hi) { int mid = (lo + hi) >> 1; if (batch[mid] < g + 1) lo = mid + 1; else hi = mid; }
    int end = lo;

    float sum = 0.f;
    for (int n = beg; n < end; n++) sum += h[(size_t)n * DIM + t];
    float cnt = (float)(end - beg);
    p[t] = sum / fmaxf(cnt, 1.0f);
    __syncthreads();

    if (t < 64) {
        float a = b1[t];
        #pragma unroll 8
        for (int k = 0; k < DIM; k++) a = fmaf(p[k], W1[k * 64 + t], a);
        hid[t] = fmaxf(a, 0.f);
    }
    __syncthreads();

    if (t < 2) {
        float a = b2[t];
        #pragma unroll 8
        for (int k = 0; k < 64; k++) a = fmaf(hid[k], W2[k * 2 + t], a);
        out[g * 2 + t] = a;
    }
}

// ---------------- launch ----------------
extern "C" void kernel_launch(void* const* d_in, const int* in_sizes, int n_in,
                              void* d_out, int out_size)
{
    const float* x     = (const float*)d_in[0];
    const int*   ei    = (const int*)d_in[1];
    const int*   batch = (const int*)d_in[2];
    const float* Wl    = (const float*)d_in[3];
    const float* bl    = (const float*)d_in[4];
    const float* Wr    = (const float*)d_in[5];
    const float* br    = (const float*)d_in[6];
    const float* att   = (const float*)d_in[7];
    const float* cb    = (const float*)d_in[8];
    const float* bng   = (const float*)d_in[9];
    const float* bnb   = (const float*)d_in[10];
    const float* bnm   = (const float*)d_in[11];
    const float* bnv   = (const float*)d_in[12];
    const float* W1    = (const float*)d_in[13];
    const float* b1    = (const float*)d_in[14];
    const float* W2    = (const float*)d_in[15];
    const float* b2    = (const float*)d_in[16];
    float* out = (float*)d_out;

    float *h0, *xl, *xr;
    __nv_bfloat16 *hhi, *hlo, *whi, *wlo;
    cudaGetSymbolAddress((void**)&h0, d_h0);
    cudaGetSymbolAddress((void**)&xl, d_xl);
    cudaGetSymbolAddress((void**)&xr, d_xr);
    cudaGetSymbolAddress((void**)&hhi, d_hhi);
    cudaGetSymbolAddress((void**)&hlo, d_hlo);
    cudaGetSymbolAddress((void**)&whi, d_whi);
    cudaGetSymbolAddress((void**)&wlo, d_wlo);

    static int smem_set = 0;
    if (!smem_set) {
        cudaFuncSetAttribute(k_gemm_tc, cudaFuncAttributeMaxDynamicSharedMemorySize, GSMEM);
        smem_set = 1;
    }

    dim3 ggrid((NODES + 127) / 128, 2);

    // order chosen so launch #3 (ncu capture slot) = k_gemm_tc layer 0
    k_convert_x<<<(NODES * DIM + 255) / 256, 256>>>(x);            // 0
    k_convert_w<<<6, 256>>>(Wl, Wr);                               // 1
    k_zero_deg<<<(NODES + 255) / 256, 256>>>();                    // 2
    k_gemm_tc<<<ggrid, 256, GSMEM>>>(hhi, hlo, whi, wlo, bl, br);  // 3  <-- profiled
    k_hist<<<(EDGES + 255) / 256, 256>>>(ei);                      // 4
    k_scan<<<1, 1024>>>();                                         // 5
    k_scatter<<<(EDGES + 255) / 256, 256>>>(ei);                   // 6

    for (int l = 0; l < 3; l++) {
        if (l > 0) {
            k_gemm_tc<<<ggrid, 256, GSMEM>>>(
                hhi, hlo,
                whi + (size_t)l * 2 * DIM * DIM, wlo + (size_t)l * 2 * DIM * DIM,
                bl + l * DIM, br + l * DIM);
        }
        k_gat<<<NODES / 8, 256>>>(xl, xr,
                                  att + l * DIM, cb + l * DIM,
                                  bng + l * DIM, bnb + l * DIM,
                                  bnm + l * DIM, bnv + l * DIM,
                                  h0, (l < 2) ? 1 : 0, (l == 2) ? 1 : 0);
    }

    k_pool_mlp<<<GRAPHS, 128>>>(h0, batch, W1, b1, W2, b2, out);
}

// round 6
// speedup vs baseline: 1.1276x; 1.1276x over previous
#include <cuda_runtime.h>
#include <cuda_bf16.h>
#include <cstdint>

#define NODES 40000
#define EDGES 640000
#define DIM 128
#define GRAPHS 512
#define NEG_SLOPE 0.2f
#define BN_EPS 1e-5f

// ---------------- scratch (no allocations allowed) ----------------
__device__ float d_h0[NODES * DIM];
__device__ float d_xl[NODES * DIM];
__device__ float d_xr[NODES * DIM];
__device__ __nv_bfloat16 d_hhi[NODES * DIM];
__device__ __nv_bfloat16 d_hlo[NODES * DIM];
__device__ __nv_bfloat16 d_whi[3 * 2 * DIM * DIM];
__device__ __nv_bfloat16 d_wlo[3 * 2 * DIM * DIM];
__device__ int d_deg[NODES];
__device__ int d_rowptr[NODES + 1];
__device__ int d_cursor[NODES];
__device__ int d_srcs[EDGES];

__device__ __forceinline__ uint32_t smem_u32(const void* p) {
    uint32_t a;
    asm("{ .reg .u64 t; cvta.to.shared.u64 t, %1; cvt.u32.u64 %0, t; }" : "=r"(a) : "l"(p));
    return a;
}
__device__ __forceinline__ void ldsm_x4(uint32_t* r, uint32_t addr) {
    asm volatile("ldmatrix.sync.aligned.m8n8.x4.shared.b16 {%0,%1,%2,%3}, [%4];"
                 : "=r"(r[0]), "=r"(r[1]), "=r"(r[2]), "=r"(r[3]) : "r"(addr));
}
__device__ __forceinline__ void ldsm_x4_t(uint32_t* r, uint32_t addr) {
    asm volatile("ldmatrix.sync.aligned.m8n8.x4.trans.shared.b16 {%0,%1,%2,%3}, [%4];"
                 : "=r"(r[0]), "=r"(r[1]), "=r"(r[2]), "=r"(r[3]) : "r"(addr));
}
__device__ __forceinline__ void mma16816(float* c, const uint32_t* a, const uint32_t* b) {
    asm volatile(
        "mma.sync.aligned.m16n8k16.row.col.f32.bf16.bf16.f32 "
        "{%0,%1,%2,%3}, {%4,%5,%6,%7}, {%8,%9}, {%0,%1,%2,%3};"
        : "+f"(c[0]), "+f"(c[1]), "+f"(c[2]), "+f"(c[3])
        : "r"(a[0]), "r"(a[1]), "r"(a[2]), "r"(a[3]), "r"(b[0]), "r"(b[1]));
}

// ---------------- CSR build ----------------
__global__ void k_zero_deg() {
    int i = blockIdx.x * blockDim.x + threadIdx.x;
    if (i < NODES) d_deg[i] = 0;
}
__global__ void k_hist(const int* __restrict__ ei) {
    int e = blockIdx.x * blockDim.x + threadIdx.x;
    if (e < EDGES) atomicAdd(&d_deg[ei[EDGES + e]], 1);
}
#define SCAN_CH 40
__global__ void k_scan() {
    __shared__ int ws[32];
    int t = threadIdx.x, lane = t & 31, wid = t >> 5;
    int base = t * SCAN_CH;
    int s = 0;
    #pragma unroll 4
    for (int k = 0; k < SCAN_CH; k++) {
        int idx = base + k;
        if (idx < NODES) s += d_deg[idx];
    }
    int x = s;
    #pragma unroll
    for (int o = 1; o < 32; o <<= 1) {
        int y = __shfl_up_sync(0xffffffffu, x, o);
        if (lane >= o) x += y;
    }
    if (lane == 31) ws[wid] = x;
    __syncthreads();
    if (wid == 0) {
        int sv = ws[lane], sx = sv;
        #pragma unroll
        for (int o = 1; o < 32; o <<= 1) {
            int y = __shfl_up_sync(0xffffffffu, sx, o);
            if (lane >= o) sx += y;
        }
        ws[lane] = sx - sv;
    }
    __syncthreads();
    int run = ws[wid] + x - s;
    #pragma unroll 4
    for (int k = 0; k < SCAN_CH; k++) {
        int idx = base + k;
        if (idx < NODES) {
            int dg = d_deg[idx];
            d_rowptr[idx] = run;
            d_cursor[idx] = run;
            run += dg;
        }
    }
    if (t == 1023) d_rowptr[NODES] = run;
}
__global__ void k_scatter(const int* __restrict__ ei) {
    int e = blockIdx.x * blockDim.x + threadIdx.x;
    if (e < EDGES) {
        int dst = ei[EDGES + e];
        int pos = atomicAdd(&d_cursor[dst], 1);
        d_srcs[pos] = ei[e];
    }
}

// ---------------- fp32 -> bf16 hi/lo converts ----------------
__global__ void k_convert_x(const float* __restrict__ x) {
    int i = blockIdx.x * blockDim.x + threadIdx.x;
    if (i < NODES * DIM) {
        float v = x[i];
        __nv_bfloat16 h = __float2bfloat16(v);
        d_hhi[i] = h;
        d_hlo[i] = __float2bfloat16(v - __bfloat162float(h));
    }
}
__global__ void k_convert_w(const float* __restrict__ Wl, const float* __restrict__ Wr) {
    int l = blockIdx.x >> 1, m = blockIdx.x & 1;
    const float* W = (m ? Wr : Wl) + (size_t)l * DIM * DIM;
    __nv_bfloat16* oh = d_whi + (size_t)(l * 2 + m) * DIM * DIM;
    __nv_bfloat16* ol = d_wlo + (size_t)(l * 2 + m) * DIM * DIM;
    for (int t = threadIdx.x; t < DIM * DIM; t += blockDim.x) {
        float v = W[t];
        __nv_bfloat16 h = __float2bfloat16(v);
        oh[t] = h;
        ol[t] = __float2bfloat16(v - __bfloat162float(h));
    }
}

// ---------------- HMMA dual GEMM (bf16x3 emulated fp32), M-tile=64, 2 CTAs/SM ----------------
#define SA_HI 0
#define SA_LO 16384
#define SW_HI 32768
#define SW_LO 65536
#define GSMEM 98304

__global__ __launch_bounds__(256, 2) void k_gemm_tc(
    const __nv_bfloat16* __restrict__ Ahi, const __nv_bfloat16* __restrict__ Alo,
    const __nv_bfloat16* __restrict__ Whi, const __nv_bfloat16* __restrict__ Wlo,
    const float* __restrict__ bl, const float* __restrict__ br)
{
    extern __shared__ char smem[];
    uint32_t sb = smem_u32(smem);
    int tid = threadIdx.x;
    int row0 = blockIdx.x * 64;
    int mat = blockIdx.y;

    const float* bias = mat ? br : bl;
    float* out = mat ? d_xr : d_xl;
    const uint4* ahi4 = (const uint4*)Ahi;
    const uint4* alo4 = (const uint4*)Alo;
    const uint4* wh4 = (const uint4*)(Whi + (size_t)mat * DIM * DIM);
    const uint4* wl4 = (const uint4*)(Wlo + (size_t)mat * DIM * DIM);

    // A: 64 rows x 16 chunks
    for (int t = tid; t < 1024; t += 256) {
        int r = t >> 4, c = t & 15;
        int so = r * 256 + (((c ^ (r & 7))) << 4);
        int grow = row0 + r;
        if (grow > NODES - 1) grow = NODES - 1;
        *(uint4*)(smem + SA_HI + so) = ahi4[grow * 16 + c];
        *(uint4*)(smem + SA_LO + so) = alo4[grow * 16 + c];
    }
    // W: 128 rows x 16 chunks
    for (int t = tid; t < 2048; t += 256) {
        int r = t >> 4, c = t & 15;
        int so = r * 256 + (((c ^ (r & 7))) << 4);
        *(uint4*)(smem + SW_HI + so) = wh4[t];
        *(uint4*)(smem + SW_LO + so) = wl4[t];
    }
    __syncthreads();

    int w = tid >> 5, lane = tid & 31;
    int mBase = (w >> 2) * 32;   // 2 row groups of 32
    int nBase = (w & 3) * 32;    // 4 col groups of 32

    float acc[2][4][4];
    #pragma unroll
    for (int mt = 0; mt < 2; mt++)
        #pragma unroll
        for (int nt = 0; nt < 4; nt++)
            #pragma unroll
            for (int j = 0; j < 4; j++) acc[mt][nt][j] = 0.f;

    int arow = lane & 15;
    int asel = lane >> 4;
    int brow_in = (lane & 7) + ((lane >> 3) & 1) * 8;
    int bsel = lane >> 4;

    #pragma unroll
    for (int ks = 0; ks < 8; ks++) {
        uint32_t ah[2][4], al[2][4];
        int achunk = ks * 2 + asel;
        #pragma unroll
        for (int mt = 0; mt < 2; mt++) {
            int r = mBase + mt * 16 + arow;
            uint32_t off = r * 256 + ((achunk ^ (r & 7)) << 4);
            ldsm_x4(ah[mt], sb + SA_HI + off);
            ldsm_x4(al[mt], sb + SA_LO + off);
        }
        uint32_t bh[2][4], bo[2][4];
        int brow = ks * 16 + brow_in;
        #pragma unroll
        for (int nt2 = 0; nt2 < 2; nt2++) {
            int chunk = ((nBase + nt2 * 16) >> 3) + bsel;
            uint32_t off = brow * 256 + ((chunk ^ (brow & 7)) << 4);
            ldsm_x4_t(bh[nt2], sb + SW_HI + off);
            ldsm_x4_t(bo[nt2], sb + SW_LO + off);
        }
        #pragma unroll
        for (int mt = 0; mt < 2; mt++)
            #pragma unroll
            for (int nt = 0; nt < 4; nt++) {
                const uint32_t* ph = &bh[nt >> 1][(nt & 1) * 2];
                const uint32_t* pl = &bo[nt >> 1][(nt & 1) * 2];
                mma16816(acc[mt][nt], ah[mt], ph);
                mma16816(acc[mt][nt], al[mt], ph);
                mma16816(acc[mt][nt], ah[mt], pl);
            }
    }

    int r0 = lane >> 2;
    int c2 = (lane & 3) * 2;
    #pragma unroll
    for (int nt = 0; nt < 4; nt++) {
        int col = nBase + nt * 8 + c2;
        float2 bi = *(const float2*)(bias + col);
        #pragma unroll
        for (int mt = 0; mt < 2; mt++) {
            int g0 = row0 + mBase + mt * 16 + r0;
            if (g0 < NODES) {
                float2 o = {acc[mt][nt][0] + bi.x, acc[mt][nt][1] + bi.y};
                *(float2*)(out + (size_t)g0 * DIM + col) = o;
            }
            int g1 = g0 + 8;
            if (g1 < NODES) {
                float2 o = {acc[mt][nt][2] + bi.x, acc[mt][nt][3] + bi.y};
                *(float2*)(out + (size_t)g1 * DIM + col) = o;
            }
        }
    }
}

// ---------------- GATv2 aggregation: fixed-shift softmax, warp per node ----------------
__device__ __forceinline__ float leaky_dot(float4 v, float4 x, float4 w) {
    float ax = v.x + x.x, ay = v.y + x.y, az = v.z + x.z, aw = v.w + x.w;
    ax = ax > 0.f ? ax : NEG_SLOPE * ax;
    ay = ay > 0.f ? ay : NEG_SLOPE * ay;
    az = az > 0.f ? az : NEG_SLOPE * az;
    aw = aw > 0.f ? aw : NEG_SLOPE * aw;
    return ax * w.x + ay * w.y + az * w.z + aw * w.w;
}
__device__ __forceinline__ float hred8(float d) {
    d += __shfl_xor_sync(0xffffffffu, d, 1);
    d += __shfl_xor_sync(0xffffffffu, d, 2);
    d += __shfl_xor_sync(0xffffffffu, d, 4);
    return d;
}

__global__ __launch_bounds__(256) void k_gat(
    const float* __restrict__ xl, const float* __restrict__ xr,
    const float* __restrict__ att, const float* __restrict__ conv_bias,
    const float* __restrict__ bn_gamma, const float* __restrict__ bn_beta,
    const float* __restrict__ bn_mean, const float* __restrict__ bn_var,
    float* __restrict__ hout, int write_bf, int write_f32)
{
    int i = blockIdx.x * 8 + (threadIdx.x >> 5);
    if (i >= NODES) return;
    int lane = threadIdx.x & 31;
    int c = lane * 4;

    float4 w   = *(const float4*)(att + c);
    float4 xr4 = *(const float4*)(xr + (size_t)i * DIM + c);

    float4 xls = *(const float4*)(xl + (size_t)i * DIM + c);
    float m0 = hred8(leaky_dot(xls, xr4, w));
    float denom = 1.0f;
    float4 acc = xls;

    int beg = d_rowptr[i];
    int end = d_rowptr[i + 1];
    int j = beg;
    for (; j + 1 < end; j += 2) {
        int s0 = d_srcs[j];
        int s1 = d_srcs[j + 1];
        float4 v0 = *(const float4*)(xl + (size_t)s0 * DIM + c);
        float4 v1 = *(const float4*)(xl + (size_t)s1 * DIM + c);
        float d0 = hred8(leaky_dot(v0, xr4, w));
        float d1 = hred8(leaky_dot(v1, xr4, w));
        float a0 = __expf(d0 - m0);
        float a1 = __expf(d1 - m0);
        denom += a0 + a1;
        acc.x += a0 * v0.x + a1 * v1.x;
        acc.y += a0 * v0.y + a1 * v1.y;
        acc.z += a0 * v0.z + a1 * v1.z;
        acc.w += a0 * v0.w + a1 * v1.w;
    }
    if (j < end) {
        int s0 = d_srcs[j];
        float4 v0 = *(const float4*)(xl + (size_t)s0 * DIM + c);
        float a0 = __expf(hred8(leaky_dot(v0, xr4, w)) - m0);
        denom += a0;
        acc.x += a0 * v0.x;
        acc.y += a0 * v0.y;
        acc.z += a0 * v0.z;
        acc.w += a0 * v0.w;
    }

    float inv = 1.0f / denom;
    float4 bias = *(const float4*)(conv_bias + c);
    float4 ga = *(const float4*)(bn_gamma + c);
    float4 be = *(const float4*)(bn_beta + c);
    float4 mu = *(const float4*)(bn_mean + c);
    float4 va = *(const float4*)(bn_var + c);
    float4 o;
    o.x = fmaxf((acc.x * inv + bias.x - mu.x) * rsqrtf(va.x + BN_EPS) * ga.x + be.x, 0.f);
    o.y = fmaxf((acc.y * inv + bias.y - mu.y) * rsqrtf(va.y + BN_EPS) * ga.y + be.y, 0.f);
    o.z = fmaxf((acc.z * inv + bias.z - mu.z) * rsqrtf(va.z + BN_EPS) * ga.z + be.z, 0.f);
    o.w = fmaxf((acc.w * inv + bias.w - mu.w) * rsqrtf(va.w + BN_EPS) * ga.w + be.w, 0.f);

    if (write_f32) *(float4*)(hout + (size_t)i * DIM + c) = o;
    if (write_bf) {
        __nv_bfloat16 hx = __float2bfloat16(o.x);
        __nv_bfloat16 hy = __float2bfloat16(o.y);
        __nv_bfloat16 hz = __float2bfloat16(o.z);
        __nv_bfloat16 hw = __float2bfloat16(o.w);
        __nv_bfloat162* ph = (__nv_bfloat162*)(d_hhi + (size_t)i * DIM + c);
        ph[0] = __nv_bfloat162(hx, hy);
        ph[1] = __nv_bfloat162(hz, hw);
        __nv_bfloat162* pl = (__nv_bfloat162*)(d_hlo + (size_t)i * DIM + c);
        pl[0] = __nv_bfloat162(__float2bfloat16(o.x - __bfloat162float(hx)),
                               __float2bfloat16(o.y - __bfloat162float(hy)));
        pl[1] = __nv_bfloat162(__float2bfloat16(o.z - __bfloat162float(hz)),
                               __float2bfloat16(o.w - __bfloat162float(hw)));
    }
}

// ---------------- mean pool (batch sorted) + MLP 128->64->2 ----------------
__global__ void k_pool_mlp(
    const float* __restrict__ h, const int* __restrict__ batch,
    const float* __restrict__ W1, const float* __restrict__ b1,
    const float* __restrict__ W2, const float* __restrict__ b2,
    float* __restrict__ out)
{
    __shared__ float p[DIM];
    __shared__ float hid[64];
    int g = blockIdx.x;
    int t = threadIdx.x;

    int lo = 0, hi = NODES;
    while (lo < hi) { int mid = (lo + hi) >> 1; if (batch[mid] < g) lo = mid + 1; else hi = mid; }
    int beg = lo;
    hi = NODES;
    while (lo < hi) { int mid = (lo + hi) >> 1; if (batch[mid] < g + 1) lo = mid + 1; else hi = mid; }
    int end = lo;

    float sum = 0.f;
    for (int n = beg; n < end; n++) sum += h[(size_t)n * DIM + t];
    float cnt = (float)(end - beg);
    p[t] = sum / fmaxf(cnt, 1.0f);
    __syncthreads();

    if (t < 64) {
        float a = b1[t];
        #pragma unroll 8
        for (int k = 0; k < DIM; k++) a = fmaf(p[k], W1[k * 64 + t], a);
        hid[t] = fmaxf(a, 0.f);
    }
    __syncthreads();

    if (t < 2) {
        float a = b2[t];
        #pragma unroll 8
        for (int k = 0; k < 64; k++) a = fmaf(hid[k], W2[k * 2 + t], a);
        out[g * 2 + t] = a;
    }
}

// ---------------- launch ----------------
extern "C" void kernel_launch(void* const* d_in, const int* in_sizes, int n_in,
                              void* d_out, int out_size)
{
    const float* x     = (const float*)d_in[0];
    const int*   ei    = (const int*)d_in[1];
    const int*   batch = (const int*)d_in[2];
    const float* Wl    = (const float*)d_in[3];
    const float* bl    = (const float*)d_in[4];
    const float* Wr    = (const float*)d_in[5];
    const float* br    = (const float*)d_in[6];
    const float* att   = (const float*)d_in[7];
    const float* cb    = (const float*)d_in[8];
    const float* bng   = (const float*)d_in[9];
    const float* bnb   = (const float*)d_in[10];
    const float* bnm   = (const float*)d_in[11];
    const float* bnv   = (const float*)d_in[12];
    const float* W1    = (const float*)d_in[13];
    const float* b1    = (const float*)d_in[14];
    const float* W2    = (const float*)d_in[15];
    const float* b2    = (const float*)d_in[16];
    float* out = (float*)d_out;

    float *h0, *xl, *xr;
    __nv_bfloat16 *hhi, *hlo, *whi, *wlo;
    cudaGetSymbolAddress((void**)&h0, d_h0);
    cudaGetSymbolAddress((void**)&xl, d_xl);
    cudaGetSymbolAddress((void**)&xr, d_xr);
    cudaGetSymbolAddress((void**)&hhi, d_hhi);
    cudaGetSymbolAddress((void**)&hlo, d_hlo);
    cudaGetSymbolAddress((void**)&whi, d_whi);
    cudaGetSymbolAddress((void**)&wlo, d_wlo);

    static int smem_set = 0;
    if (!smem_set) {
        cudaFuncSetAttribute(k_gemm_tc, cudaFuncAttributeMaxDynamicSharedMemorySize, GSMEM);
        smem_set = 1;
    }

    dim3 ggrid(NODES / 64, 2);

    // order: launch #3 (ncu capture slot) = k_gemm_tc layer 0
    k_convert_x<<<(NODES * DIM + 255) / 256, 256>>>(x);            // 0
    k_convert_w<<<6, 256>>>(Wl, Wr);                               // 1
    k_zero_deg<<<(NODES + 255) / 256, 256>>>();                    // 2
    k_gemm_tc<<<ggrid, 256, GSMEM>>>(hhi, hlo, whi, wlo, bl, br);  // 3  <-- profiled
    k_hist<<<(EDGES + 255) / 256, 256>>>(ei);                      // 4
    k_scan<<<1, 1024>>>();                                         // 5
    k_scatter<<<(EDGES + 255) / 256, 256>>>(ei);                   // 6

    for (int l = 0; l < 3; l++) {
        if (l > 0) {
            k_gemm_tc<<<ggrid, 256, GSMEM>>>(
                hhi, hlo,
                whi + (size_t)l * 2 * DIM * DIM, wlo + (size_t)l * 2 * DIM * DIM,
                bl + l * DIM, br + l * DIM);
        }
        k_gat<<<NODES / 8, 256>>>(xl, xr,
                                  att + l * DIM, cb + l * DIM,
                                  bng + l * DIM, bnb + l * DIM,
                                  bnm + l * DIM, bnv + l * DIM,
                                  h0, (l < 2) ? 1 : 0, (l == 2) ? 1 : 0);
    }

    k_pool_mlp<<<GRAPHS, 128>>>(h0, batch, W1, b1, W2, b2, out);
}

// round 7
// speedup vs baseline: 1.2293x; 1.0902x over previous
#include <cuda_runtime.h>
#include <cuda_bf16.h>
#include <cstdint>

#define NODES 40000
#define EDGES 640000
#define DIM 128
#define GRAPHS 512
#define NEG_SLOPE 0.2f
#define BN_EPS 1e-5f

// ---------------- scratch (no allocations allowed) ----------------
__device__ float d_h0[NODES * DIM];
__device__ float d_xl[NODES * DIM];
__device__ float d_xr[NODES * DIM];
__device__ __nv_bfloat16 d_hhi[NODES * DIM];
__device__ __nv_bfloat16 d_hlo[NODES * DIM];
__device__ __nv_bfloat16 d_whi[3 * 2 * DIM * DIM];
__device__ __nv_bfloat16 d_wlo[3 * 2 * DIM * DIM];
__device__ int d_deg[NODES];
__device__ int d_rowptr[NODES + 1];
__device__ int d_cursor[NODES];
__device__ int d_srcs[EDGES];

__device__ __forceinline__ uint32_t smem_u32(const void* p) {
    uint32_t a;
    asm("{ .reg .u64 t; cvta.to.shared.u64 t, %1; cvt.u32.u64 %0, t; }" : "=r"(a) : "l"(p));
    return a;
}
__device__ __forceinline__ void ldsm_x4(uint32_t* r, uint32_t addr) {
    asm volatile("ldmatrix.sync.aligned.m8n8.x4.shared.b16 {%0,%1,%2,%3}, [%4];"
                 : "=r"(r[0]), "=r"(r[1]), "=r"(r[2]), "=r"(r[3]) : "r"(addr));
}
__device__ __forceinline__ void ldsm_x4_t(uint32_t* r, uint32_t addr) {
    asm volatile("ldmatrix.sync.aligned.m8n8.x4.trans.shared.b16 {%0,%1,%2,%3}, [%4];"
                 : "=r"(r[0]), "=r"(r[1]), "=r"(r[2]), "=r"(r[3]) : "r"(addr));
}
__device__ __forceinline__ void mma16816(float* c, const uint32_t* a, const uint32_t* b) {
    asm volatile(
        "mma.sync.aligned.m16n8k16.row.col.f32.bf16.bf16.f32 "
        "{%0,%1,%2,%3}, {%4,%5,%6,%7}, {%8,%9}, {%0,%1,%2,%3};"
        : "+f"(c[0]), "+f"(c[1]), "+f"(c[2]), "+f"(c[3])
        : "r"(a[0]), "r"(a[1]), "r"(a[2]), "r"(a[3]), "r"(b[0]), "r"(b[1]));
}
__device__ __forceinline__ void cp16(uint32_t saddr, const void* gaddr) {
    asm volatile("cp.async.cg.shared.global [%0], [%1], 16;" :: "r"(saddr), "l"(gaddr));
}
#define CP_COMMIT() asm volatile("cp.async.commit_group;" ::: "memory")
#define CP_WAIT0()  asm volatile("cp.async.wait_group 0;" ::: "memory")

// ---------------- CSR build ----------------
__global__ void k_zero_deg() {
    int i = blockIdx.x * blockDim.x + threadIdx.x;
    if (i < NODES) d_deg[i] = 0;
}
__global__ void k_hist(const int* __restrict__ ei) {
    int e = blockIdx.x * blockDim.x + threadIdx.x;
    if (e < EDGES) atomicAdd(&d_deg[ei[EDGES + e]], 1);
}
#define SCAN_CH 40
__global__ void k_scan() {
    __shared__ int ws[32];
    int t = threadIdx.x, lane = t & 31, wid = t >> 5;
    int base = t * SCAN_CH;
    int s = 0;
    #pragma unroll 4
    for (int k = 0; k < SCAN_CH; k++) {
        int idx = base + k;
        if (idx < NODES) s += d_deg[idx];
    }
    int x = s;
    #pragma unroll
    for (int o = 1; o < 32; o <<= 1) {
        int y = __shfl_up_sync(0xffffffffu, x, o);
        if (lane >= o) x += y;
    }
    if (lane == 31) ws[wid] = x;
    __syncthreads();
    if (wid == 0) {
        int sv = ws[lane], sx = sv;
        #pragma unroll
        for (int o = 1; o < 32; o <<= 1) {
            int y = __shfl_up_sync(0xffffffffu, sx, o);
            if (lane >= o) sx += y;
        }
        ws[lane] = sx - sv;
    }
    __syncthreads();
    int run = ws[wid] + x - s;
    #pragma unroll 4
    for (int k = 0; k < SCAN_CH; k++) {
        int idx = base + k;
        if (idx < NODES) {
            int dg = d_deg[idx];
            d_rowptr[idx] = run;
            d_cursor[idx] = run;
            run += dg;
        }
    }
    if (t == 1023) d_rowptr[NODES] = run;
}
__global__ void k_scatter(const int* __restrict__ ei) {
    int e = blockIdx.x * blockDim.x + threadIdx.x;
    if (e < EDGES) {
        int dst = ei[EDGES + e];
        int pos = atomicAdd(&d_cursor[dst], 1);
        d_srcs[pos] = ei[e];
    }
}

// ---------------- fp32 -> bf16 hi/lo converts ----------------
__global__ void k_convert_x(const float* __restrict__ x) {
    int i = blockIdx.x * blockDim.x + threadIdx.x;
    if (i < NODES * DIM) {
        float v = x[i];
        __nv_bfloat16 h = __float2bfloat16(v);
        d_hhi[i] = h;
        d_hlo[i] = __float2bfloat16(v - __bfloat162float(h));
    }
}
__global__ void k_convert_w(const float* __restrict__ Wl, const float* __restrict__ Wr) {
    int l = blockIdx.x >> 1, m = blockIdx.x & 1;
    const float* W = (m ? Wr : Wl) + (size_t)l * DIM * DIM;
    __nv_bfloat16* oh = d_whi + (size_t)(l * 2 + m) * DIM * DIM;
    __nv_bfloat16* ol = d_wlo + (size_t)(l * 2 + m) * DIM * DIM;
    for (int t = threadIdx.x; t < DIM * DIM; t += blockDim.x) {
        float v = W[t];
        __nv_bfloat16 h = __float2bfloat16(v);
        oh[t] = h;
        ol[t] = __float2bfloat16(v - __bfloat162float(h));
    }
}

// ---------------- persistent HMMA dual GEMM (bf16x3), W resident, cp.async A pipe ----------------
#define SW_HI 0
#define SW_LO 32768
#define SA_BUF 65536        // 2 x (A_hi 16KB + A_lo 16KB)
#define ABUF_SZ 32768
#define GSMEM 131072
#define NTILES (NODES / 64) // 625

__global__ __launch_bounds__(256, 1) void k_gemm_tc(
    const __nv_bfloat16* __restrict__ Ahi, const __nv_bfloat16* __restrict__ Alo,
    const __nv_bfloat16* __restrict__ Whi, const __nv_bfloat16* __restrict__ Wlo,
    const float* __restrict__ bl, const float* __restrict__ br)
{
    extern __shared__ char smem[];
    uint32_t sb = smem_u32(smem);
    int tid = threadIdx.x;
    int mat = blockIdx.y;

    const float* bias = mat ? br : bl;
    float* out = mat ? d_xr : d_xl;
    const uint4* ahi4 = (const uint4*)Ahi;
    const uint4* alo4 = (const uint4*)Alo;
    const uint4* wh4 = (const uint4*)(Whi + (size_t)mat * DIM * DIM);
    const uint4* wl4 = (const uint4*)(Wlo + (size_t)mat * DIM * DIM);

    // ---- prologue: W (resident) + first A tile via cp.async ----
    int tb0 = blockIdx.x;
    // W: 2048 uint4 hi + 2048 lo
    for (int t = tid; t < 2048; t += 256) {
        int r = t >> 4, c = t & 15;
        uint32_t so = r * 256 + ((c ^ (r & 7)) << 4);
        cp16(sb + SW_HI + so, wh4 + t);
        cp16(sb + SW_LO + so, wl4 + t);
    }
    if (tb0 < NTILES) {
        int row0 = tb0 * 64;
        for (int t = tid; t < 1024; t += 256) {
            int r = t >> 4, c = t & 15;
            uint32_t so = r * 256 + ((c ^ (r & 7)) << 4);
            cp16(sb + SA_BUF + so, ahi4 + (row0 + r) * 16 + c);
            cp16(sb + SA_BUF + 16384 + so, alo4 + (row0 + r) * 16 + c);
        }
    }
    CP_COMMIT();
    CP_WAIT0();
    __syncthreads();

    int w = tid >> 5, lane = tid & 31;
    int mBase = (w >> 2) * 32;
    int nBase = (w & 3) * 32;
    int arow = lane & 15;
    int asel = lane >> 4;
    int brow_in = (lane & 7) + ((lane >> 3) & 1) * 8;
    int bsel = lane >> 4;
    int r0 = lane >> 2;
    int c2 = (lane & 3) * 2;

    int buf = 0;
    for (int tb = tb0; tb < NTILES; tb += gridDim.x) {
        int tn = tb + gridDim.x;
        // kick next A tile into the other buffer
        if (tn < NTILES) {
            uint32_t ab = sb + SA_BUF + (buf ^ 1) * ABUF_SZ;
            int rown = tn * 64;
            for (int t = tid; t < 1024; t += 256) {
                int r = t >> 4, c = t & 15;
                uint32_t so = r * 256 + ((c ^ (r & 7)) << 4);
                cp16(ab + so, ahi4 + (rown + r) * 16 + c);
                cp16(ab + 16384 + so, alo4 + (rown + r) * 16 + c);
            }
        }
        CP_COMMIT();

        // ---- compute current tile ----
        uint32_t sa_hi = sb + SA_BUF + buf * ABUF_SZ;
        uint32_t sa_lo = sa_hi + 16384;

        float acc[2][4][4];
        #pragma unroll
        for (int mt = 0; mt < 2; mt++)
            #pragma unroll
            for (int nt = 0; nt < 4; nt++)
                #pragma unroll
                for (int j = 0; j < 4; j++) acc[mt][nt][j] = 0.f;

        #pragma unroll
        for (int ks = 0; ks < 8; ks++) {
            uint32_t ah[2][4], al[2][4];
            int achunk = ks * 2 + asel;
            #pragma unroll
            for (int mt = 0; mt < 2; mt++) {
                int r = mBase + mt * 16 + arow;
                uint32_t off = r * 256 + ((achunk ^ (r & 7)) << 4);
                ldsm_x4(ah[mt], sa_hi + off);
                ldsm_x4(al[mt], sa_lo + off);
            }
            uint32_t bh[2][4], bo[2][4];
            int brow = ks * 16 + brow_in;
            #pragma unroll
            for (int nt2 = 0; nt2 < 2; nt2++) {
                int chunk = ((nBase + nt2 * 16) >> 3) + bsel;
                uint32_t off = brow * 256 + ((chunk ^ (brow & 7)) << 4);
                ldsm_x4_t(bh[nt2], sb + SW_HI + off);
                ldsm_x4_t(bo[nt2], sb + SW_LO + off);
            }
            #pragma unroll
            for (int mt = 0; mt < 2; mt++)
                #pragma unroll
                for (int nt = 0; nt < 4; nt++) {
                    const uint32_t* ph = &bh[nt >> 1][(nt & 1) * 2];
                    const uint32_t* pl = &bo[nt >> 1][(nt & 1) * 2];
                    mma16816(acc[mt][nt], ah[mt], ph);
                    mma16816(acc[mt][nt], al[mt], ph);
                    mma16816(acc[mt][nt], ah[mt], pl);
                }
        }

        // epilogue: + bias, stores (tile fully in range: 625*64 == NODES)
        int row0 = tb * 64;
        #pragma unroll
        for (int nt = 0; nt < 4; nt++) {
            int col = nBase + nt * 8 + c2;
            float2 bi = *(const float2*)(bias + col);
            #pragma unroll
            for (int mt = 0; mt < 2; mt++) {
                int g0 = row0 + mBase + mt * 16 + r0;
                float2 o0 = {acc[mt][nt][0] + bi.x, acc[mt][nt][1] + bi.y};
                *(float2*)(out + (size_t)g0 * DIM + col) = o0;
                float2 o1 = {acc[mt][nt][2] + bi.x, acc[mt][nt][3] + bi.y};
                *(float2*)(out + (size_t)(g0 + 8) * DIM + col) = o1;
            }
        }

        CP_WAIT0();
        __syncthreads();
        buf ^= 1;
    }
}

// ---------------- GATv2 aggregation: fixed-shift softmax, warp per node ----------------
__device__ __forceinline__ float leaky_dot(float4 v, float4 x, float4 w) {
    float ax = v.x + x.x, ay = v.y + x.y, az = v.z + x.z, aw = v.w + x.w;
    ax = ax > 0.f ? ax : NEG_SLOPE * ax;
    ay = ay > 0.f ? ay : NEG_SLOPE * ay;
    az = az > 0.f ? az : NEG_SLOPE * az;
    aw = aw > 0.f ? aw : NEG_SLOPE * aw;
    return ax * w.x + ay * w.y + az * w.z + aw * w.w;
}
__device__ __forceinline__ float hred8(float d) {
    d += __shfl_xor_sync(0xffffffffu, d, 1);
    d += __shfl_xor_sync(0xffffffffu, d, 2);
    d += __shfl_xor_sync(0xffffffffu, d, 4);
    return d;
}

__global__ __launch_bounds__(256) void k_gat(
    const float* __restrict__ xl, const float* __restrict__ xr,
    const float* __restrict__ att, const float* __restrict__ conv_bias,
    const float* __restrict__ bn_gamma, const float* __restrict__ bn_beta,
    const float* __restrict__ bn_mean, const float* __restrict__ bn_var,
    float* __restrict__ hout, int write_bf, int write_f32)
{
    int i = blockIdx.x * 8 + (threadIdx.x >> 5);
    if (i >= NODES) return;
    int lane = threadIdx.x & 31;
    int c = lane * 4;

    float4 w   = *(const float4*)(att + c);
    float4 xr4 = *(const float4*)(xr + (size_t)i * DIM + c);

    float4 xls = *(const float4*)(xl + (size_t)i * DIM + c);
    float m0 = hred8(leaky_dot(xls, xr4, w));
    float denom = 1.0f;
    float4 acc = xls;

    int beg = d_rowptr[i];
    int end = d_rowptr[i + 1];
    int j = beg;
    for (; j + 1 < end; j += 2) {
        int s0 = d_srcs[j];
        int s1 = d_srcs[j + 1];
        float4 v0 = *(const float4*)(xl + (size_t)s0 * DIM + c);
        float4 v1 = *(const float4*)(xl + (size_t)s1 * DIM + c);
        float d0 = hred8(leaky_dot(v0, xr4, w));
        float d1 = hred8(leaky_dot(v1, xr4, w));
        float a0 = __expf(d0 - m0);
        float a1 = __expf(d1 - m0);
        denom += a0 + a1;
        acc.x += a0 * v0.x + a1 * v1.x;
        acc.y += a0 * v0.y + a1 * v1.y;
        acc.z += a0 * v0.z + a1 * v1.z;
        acc.w += a0 * v0.w + a1 * v1.w;
    }
    if (j < end) {
        int s0 = d_srcs[j];
        float4 v0 = *(const float4*)(xl + (size_t)s0 * DIM + c);
        float a0 = __expf(hred8(leaky_dot(v0, xr4, w)) - m0);
        denom += a0;
        acc.x += a0 * v0.x;
        acc.y += a0 * v0.y;
        acc.z += a0 * v0.z;
        acc.w += a0 * v0.w;
    }

    float inv = 1.0f / denom;
    float4 bias = *(const float4*)(conv_bias + c);
    float4 ga = *(const float4*)(bn_gamma + c);
    float4 be = *(const float4*)(bn_beta + c);
    float4 mu = *(const float4*)(bn_mean + c);
    float4 va = *(const float4*)(bn_var + c);
    float4 o;
    o.x = fmaxf((acc.x * inv + bias.x - mu.x) * rsqrtf(va.x + BN_EPS) * ga.x + be.x, 0.f);
    o.y = fmaxf((acc.y * inv + bias.y - mu.y) * rsqrtf(va.y + BN_EPS) * ga.y + be.y, 0.f);
    o.z = fmaxf((acc.z * inv + bias.z - mu.z) * rsqrtf(va.z + BN_EPS) * ga.z + be.z, 0.f);
    o.w = fmaxf((acc.w * inv + bias.w - mu.w) * rsqrtf(va.w + BN_EPS) * ga.w + be.w, 0.f);

    if (write_f32) *(float4*)(hout + (size_t)i * DIM + c) = o;
    if (write_bf) {
        __nv_bfloat16 hx = __float2bfloat16(o.x);
        __nv_bfloat16 hy = __float2bfloat16(o.y);
        __nv_bfloat16 hz = __float2bfloat16(o.z);
        __nv_bfloat16 hw = __float2bfloat16(o.w);
        __nv_bfloat162* ph = (__nv_bfloat162*)(d_hhi + (size_t)i * DIM + c);
        ph[0] = __nv_bfloat162(hx, hy);
        ph[1] = __nv_bfloat162(hz, hw);
        __nv_bfloat162* pl = (__nv_bfloat162*)(d_hlo + (size_t)i * DIM + c);
        pl[0] = __nv_bfloat162(__float2bfloat16(o.x - __bfloat162float(hx)),
                               __float2bfloat16(o.y - __bfloat162float(hy)));
        pl[1] = __nv_bfloat162(__float2bfloat16(o.z - __bfloat162float(hz)),
                               __float2bfloat16(o.w - __bfloat162float(hw)));
    }
}

// ---------------- mean pool (batch sorted) + MLP 128->64->2 ----------------
__global__ void k_pool_mlp(
    const float* __restrict__ h, const int* __restrict__ batch,
    const float* __restrict__ W1, const float* __restrict__ b1,
    const float* __restrict__ W2, const float* __restrict__ b2,
    float* __restrict__ out)
{
    __shared__ float p[DIM];
    __shared__ float hid[64];
    int g = blockIdx.x;
    int t = threadIdx.x;

    int lo = 0, hi = NODES;
    while (lo < hi) { int mid = (lo + hi) >> 1; if (batch[mid] < g) lo = mid + 1; else hi = mid; }
    int beg = lo;
    hi = NODES;
    while (lo < hi) { int mid = (lo + hi) >> 1; if (batch[mid] < g + 1) lo = mid + 1; else hi = mid; }
    int end = lo;

    float sum = 0.f;
    for (int n = beg; n < end; n++) sum += h[(size_t)n * DIM + t];
    float cnt = (float)(end - beg);
    p[t] = sum / fmaxf(cnt, 1.0f);
    __syncthreads();

    if (t < 64) {
        float a = b1[t];
        #pragma unroll 8
        for (int k = 0; k < DIM; k++) a = fmaf(p[k], W1[k * 64 + t], a);
        hid[t] = fmaxf(a, 0.f);
    }
    __syncthreads();

    if (t < 2) {
        float a = b2[t];
        #pragma unroll 8
        for (int k = 0; k < 64; k++) a = fmaf(hid[k], W2[k * 2 + t], a);
        out[g * 2 + t] = a;
    }
}

// ---------------- launch ----------------
extern "C" void kernel_launch(void* const* d_in, const int* in_sizes, int n_in,
                              void* d_out, int out_size)
{
    const float* x     = (const float*)d_in[0];
    const int*   ei    = (const int*)d_in[1];
    const int*   batch = (const int*)d_in[2];
    const float* Wl    = (const float*)d_in[3];
    const float* bl    = (const float*)d_in[4];
    const float* Wr    = (const float*)d_in[5];
    const float* br    = (const float*)d_in[6];
    const float* att   = (const float*)d_in[7];
    const float* cb    = (const float*)d_in[8];
    const float* bng   = (const float*)d_in[9];
    const float* bnb   = (const float*)d_in[10];
    const float* bnm   = (const float*)d_in[11];
    const float* bnv   = (const float*)d_in[12];
    const float* W1    = (const float*)d_in[13];
    const float* b1    = (const float*)d_in[14];
    const float* W2    = (const float*)d_in[15];
    const float* b2    = (const float*)d_in[16];
    float* out = (float*)d_out;

    float *h0, *xl, *xr;
    __nv_bfloat16 *hhi, *hlo, *whi, *wlo;
    cudaGetSymbolAddress((void**)&h0, d_h0);
    cudaGetSymbolAddress((void**)&xl, d_xl);
    cudaGetSymbolAddress((void**)&xr, d_xr);
    cudaGetSymbolAddress((void**)&hhi, d_hhi);
    cudaGetSymbolAddress((void**)&hlo, d_hlo);
    cudaGetSymbolAddress((void**)&whi, d_whi);
    cudaGetSymbolAddress((void**)&wlo, d_wlo);

    static int smem_set = 0;
    if (!smem_set) {
        cudaFuncSetAttribute(k_gemm_tc, cudaFuncAttributeMaxDynamicSharedMemorySize, GSMEM);
        smem_set = 1;
    }

    dim3 ggrid(74, 2);

    // order: launch #3 (ncu capture slot) = k_gemm_tc layer 0
    k_convert_x<<<(NODES * DIM + 255) / 256, 256>>>(x);            // 0
    k_convert_w<<<6, 256>>>(Wl, Wr);                               // 1
    k_zero_deg<<<(NODES + 255) / 256, 256>>>();                    // 2
    k_gemm_tc<<<ggrid, 256, GSMEM>>>(hhi, hlo, whi, wlo, bl, br);  // 3  <-- profiled
    k_hist<<<(EDGES + 255) / 256, 256>>>(ei);                      // 4
    k_scan<<<1, 1024>>>();                                         // 5
    k_scatter<<<(EDGES + 255) / 256, 256>>>(ei);                   // 6

    for (int l = 0; l < 3; l++) {
        if (l > 0) {
            k_gemm_tc<<<ggrid, 256, GSMEM>>>(
                hhi, hlo,
                whi + (size_t)l * 2 * DIM * DIM, wlo + (size_t)l * 2 * DIM * DIM,
                bl + l * DIM, br + l * DIM);
        }
        k_gat<<<NODES / 8, 256>>>(xl, xr,
                                  att + l * DIM, cb + l * DIM,
                                  bng + l * DIM, bnb + l * DIM,
                                  bnm + l * DIM, bnv + l * DIM,
                                  h0, (l < 2) ? 1 : 0, (l == 2) ? 1 : 0);
    }

    k_pool_mlp<<<GRAPHS, 128>>>(h0, batch, W1, b1, W2, b2, out);
}

// round 8
// speedup vs baseline: 1.2545x; 1.0205x over previous
#include <cuda_runtime.h>
#include <cuda_bf16.h>
#include <cstdint>

#define NODES 40000
#define EDGES 640000
#define DIM 128
#define GRAPHS 512
#define NEG_SLOPE 0.2f
#define BN_EPS 1e-5f

// ---------------- scratch (no allocations allowed) ----------------
__device__ float d_h0[NODES * DIM];
__device__ float d_xl[NODES * DIM];
__device__ float d_xr[NODES * DIM];
__device__ __nv_bfloat16 d_hhi[NODES * DIM];
__device__ __nv_bfloat16 d_hlo[NODES * DIM];
__device__ __nv_bfloat16 d_whi[3 * 2 * DIM * DIM];
__device__ __nv_bfloat16 d_wlo[3 * 2 * DIM * DIM];
__device__ int d_deg[NODES];
__device__ int d_rowptr[NODES + 1];
__device__ int d_cursor[NODES];
__device__ int d_srcs[EDGES];

__device__ __forceinline__ uint32_t smem_u32(const void* p) {
    uint32_t a;
    asm("{ .reg .u64 t; cvta.to.shared.u64 t, %1; cvt.u32.u64 %0, t; }" : "=r"(a) : "l"(p));
    return a;
}
__device__ __forceinline__ void ldsm_x4(uint32_t* r, uint32_t addr) {
    asm volatile("ldmatrix.sync.aligned.m8n8.x4.shared.b16 {%0,%1,%2,%3}, [%4];"
                 : "=r"(r[0]), "=r"(r[1]), "=r"(r[2]), "=r"(r[3]) : "r"(addr));
}
__device__ __forceinline__ void ldsm_x4_t(uint32_t* r, uint32_t addr) {
    asm volatile("ldmatrix.sync.aligned.m8n8.x4.trans.shared.b16 {%0,%1,%2,%3}, [%4];"
                 : "=r"(r[0]), "=r"(r[1]), "=r"(r[2]), "=r"(r[3]) : "r"(addr));
}
__device__ __forceinline__ void mma16816(float* c, const uint32_t* a, const uint32_t* b) {
    asm volatile(
        "mma.sync.aligned.m16n8k16.row.col.f32.bf16.bf16.f32 "
        "{%0,%1,%2,%3}, {%4,%5,%6,%7}, {%8,%9}, {%0,%1,%2,%3};"
        : "+f"(c[0]), "+f"(c[1]), "+f"(c[2]), "+f"(c[3])
        : "r"(a[0]), "r"(a[1]), "r"(a[2]), "r"(a[3]), "r"(b[0]), "r"(b[1]));
}
__device__ __forceinline__ void cp16(uint32_t saddr, const void* gaddr) {
    asm volatile("cp.async.cg.shared.global [%0], [%1], 16;" :: "r"(saddr), "l"(gaddr));
}
#define CP_COMMIT() asm volatile("cp.async.commit_group;" ::: "memory")
#define CP_WAIT0()  asm volatile("cp.async.wait_group 0;" ::: "memory")

// ---------------- fused: convert x to bf16 hi/lo + zero deg ----------------
__global__ void k_convx_zero(const float* __restrict__ x) {
    int i = blockIdx.x * blockDim.x + threadIdx.x;
    if (i < NODES * DIM) {
        float v = x[i];
        __nv_bfloat16 h = __float2bfloat16(v);
        d_hhi[i] = h;
        d_hlo[i] = __float2bfloat16(v - __bfloat162float(h));
    }
    if (i < NODES) d_deg[i] = 0;
}

// ---------------- fused: degree histogram + convert weights ----------------
#define HIST_BLOCKS (EDGES / 256)   // 2500
__global__ void k_hist_cw(const int* __restrict__ ei,
                          const float* __restrict__ Wl, const float* __restrict__ Wr) {
    if (blockIdx.x < HIST_BLOCKS) {
        int e = blockIdx.x * blockDim.x + threadIdx.x;
        atomicAdd(&d_deg[ei[EDGES + e]], 1);
    } else {
        int b = blockIdx.x - HIST_BLOCKS;   // 0..5
        int l = b >> 1, m = b & 1;
        const float* W = (m ? Wr : Wl) + (size_t)l * DIM * DIM;
        __nv_bfloat16* oh = d_whi + (size_t)(l * 2 + m) * DIM * DIM;
        __nv_bfloat16* ol = d_wlo + (size_t)(l * 2 + m) * DIM * DIM;
        for (int t = threadIdx.x; t < DIM * DIM; t += blockDim.x) {
            float v = W[t];
            __nv_bfloat16 h = __float2bfloat16(v);
            oh[t] = h;
            ol[t] = __float2bfloat16(v - __bfloat162float(h));
        }
    }
}

#define SCAN_CH 40
__global__ void k_scan() {
    __shared__ int ws[32];
    int t = threadIdx.x, lane = t & 31, wid = t >> 5;
    int base = t * SCAN_CH;
    int s = 0;
    #pragma unroll 4
    for (int k = 0; k < SCAN_CH; k++) {
        int idx = base + k;
        if (idx < NODES) s += d_deg[idx];
    }
    int x = s;
    #pragma unroll
    for (int o = 1; o < 32; o <<= 1) {
        int y = __shfl_up_sync(0xffffffffu, x, o);
        if (lane >= o) x += y;
    }
    if (lane == 31) ws[wid] = x;
    __syncthreads();
    if (wid == 0) {
        int sv = ws[lane], sx = sv;
        #pragma unroll
        for (int o = 1; o < 32; o <<= 1) {
            int y = __shfl_up_sync(0xffffffffu, sx, o);
            if (lane >= o) sx += y;
        }
        ws[lane] = sx - sv;
    }
    __syncthreads();
    int run = ws[wid] + x - s;
    #pragma unroll 4
    for (int k = 0; k < SCAN_CH; k++) {
        int idx = base + k;
        if (idx < NODES) {
            int dg = d_deg[idx];
            d_rowptr[idx] = run;
            d_cursor[idx] = run;
            run += dg;
        }
    }
    if (t == 1023) d_rowptr[NODES] = run;
}
__global__ void k_scatter(const int* __restrict__ ei) {
    int e = blockIdx.x * blockDim.x + threadIdx.x;
    if (e < EDGES) {
        int dst = ei[EDGES + e];
        int pos = atomicAdd(&d_cursor[dst], 1);
        d_srcs[pos] = ei[e];
    }
}

// ---------------- persistent HMMA dual GEMM, W resident, cp.async A pipe, frag pipeline ----------------
#define SW_HI 0
#define SW_LO 32768
#define SA_BUF 65536
#define ABUF_SZ 32768
#define GSMEM 131072
#define NTILES (NODES / 64)

__global__ __launch_bounds__(256, 1) void k_gemm_tc(
    const __nv_bfloat16* __restrict__ Ahi, const __nv_bfloat16* __restrict__ Alo,
    const __nv_bfloat16* __restrict__ Whi, const __nv_bfloat16* __restrict__ Wlo,
    const float* __restrict__ bl, const float* __restrict__ br)
{
    extern __shared__ char smem[];
    uint32_t sb = smem_u32(smem);
    int tid = threadIdx.x;
    int mat = blockIdx.y;

    const float* bias = mat ? br : bl;
    float* out = mat ? d_xr : d_xl;
    const uint4* ahi4 = (const uint4*)Ahi;
    const uint4* alo4 = (const uint4*)Alo;
    const uint4* wh4 = (const uint4*)(Whi + (size_t)mat * DIM * DIM);
    const uint4* wl4 = (const uint4*)(Wlo + (size_t)mat * DIM * DIM);

    int tb0 = blockIdx.x;
    for (int t = tid; t < 2048; t += 256) {
        int r = t >> 4, c = t & 15;
        uint32_t so = r * 256 + ((c ^ (r & 7)) << 4);
        cp16(sb + SW_HI + so, wh4 + t);
        cp16(sb + SW_LO + so, wl4 + t);
    }
    if (tb0 < NTILES) {
        int row0 = tb0 * 64;
        for (int t = tid; t < 1024; t += 256) {
            int r = t >> 4, c = t & 15;
            uint32_t so = r * 256 + ((c ^ (r & 7)) << 4);
            cp16(sb + SA_BUF + so, ahi4 + (row0 + r) * 16 + c);
            cp16(sb + SA_BUF + 16384 + so, alo4 + (row0 + r) * 16 + c);
        }
    }
    CP_COMMIT();
    CP_WAIT0();
    __syncthreads();

    int w = tid >> 5, lane = tid & 31;
    int mBase = (w >> 2) * 32;
    int nBase = (w & 3) * 32;
    int arow = lane & 15;
    int asel = lane >> 4;
    int brow_in = (lane & 7) + ((lane >> 3) & 1) * 8;
    int bsel = lane >> 4;
    int r0 = lane >> 2;
    int c2 = (lane & 3) * 2;

    int buf = 0;
    for (int tb = tb0; tb < NTILES; tb += gridDim.x) {
        int tn = tb + gridDim.x;
        if (tn < NTILES) {
            uint32_t ab = sb + SA_BUF + (buf ^ 1) * ABUF_SZ;
            int rown = tn * 64;
            for (int t = tid; t < 1024; t += 256) {
                int r = t >> 4, c = t & 15;
                uint32_t so = r * 256 + ((c ^ (r & 7)) << 4);
                cp16(ab + so, ahi4 + (rown + r) * 16 + c);
                cp16(ab + 16384 + so, alo4 + (rown + r) * 16 + c);
            }
        }
        CP_COMMIT();

        uint32_t sa_hi = sb + SA_BUF + buf * ABUF_SZ;
        uint32_t sa_lo = sa_hi + 16384;

        float acc[2][4][4];
        #pragma unroll
        for (int mt = 0; mt < 2; mt++)
            #pragma unroll
            for (int nt = 0; nt < 4; nt++)
                #pragma unroll
                for (int j = 0; j < 4; j++) acc[mt][nt][j] = 0.f;

        // fragment double buffers
        uint32_t ah[2][2][4], al[2][2][4], bh[2][2][4], bo[2][2][4];

        // prologue: load ks=0 fragments
        {
            int achunk = asel;
            #pragma unroll
            for (int mt = 0; mt < 2; mt++) {
                int r = mBase + mt * 16 + arow;
                uint32_t off = r * 256 + ((achunk ^ (r & 7)) << 4);
                ldsm_x4(ah[0][mt], sa_hi + off);
                ldsm_x4(al[0][mt], sa_lo + off);
            }
            int brow = brow_in;
            #pragma unroll
            for (int nt2 = 0; nt2 < 2; nt2++) {
                int chunk = ((nBase + nt2 * 16) >> 3) + bsel;
                uint32_t off = brow * 256 + ((chunk ^ (brow & 7)) << 4);
                ldsm_x4_t(bh[0][nt2], sb + SW_HI + off);
                ldsm_x4_t(bo[0][nt2], sb + SW_LO + off);
            }
        }

        #pragma unroll
        for (int ks = 0; ks < 8; ks++) {
            int fb = ks & 1;
            if (ks < 7) {
                int kn = ks + 1;
                int achunk = kn * 2 + asel;
                #pragma unroll
                for (int mt = 0; mt < 2; mt++) {
                    int r = mBase + mt * 16 + arow;
                    uint32_t off = r * 256 + ((achunk ^ (r & 7)) << 4);
                    ldsm_x4(ah[fb ^ 1][mt], sa_hi + off);
                    ldsm_x4(al[fb ^ 1][mt], sa_lo + off);
                }
                int brow = kn * 16 + brow_in;
                #pragma unroll
                for (int nt2 = 0; nt2 < 2; nt2++) {
                    int chunk = ((nBase + nt2 * 16) >> 3) + bsel;
                    uint32_t off = brow * 256 + ((chunk ^ (brow & 7)) << 4);
                    ldsm_x4_t(bh[fb ^ 1][nt2], sb + SW_HI + off);
                    ldsm_x4_t(bo[fb ^ 1][nt2], sb + SW_LO + off);
                }
            }
            #pragma unroll
            for (int mt = 0; mt < 2; mt++)
                #pragma unroll
                for (int nt = 0; nt < 4; nt++) {
                    const uint32_t* ph = &bh[fb][nt >> 1][(nt & 1) * 2];
                    const uint32_t* pl = &bo[fb][nt >> 1][(nt & 1) * 2];
                    mma16816(acc[mt][nt], ah[fb][mt], ph);
                    mma16816(acc[mt][nt], al[fb][mt], ph);
                    mma16816(acc[mt][nt], ah[fb][mt], pl);
                }
        }

        int row0 = tb * 64;
        #pragma unroll
        for (int nt = 0; nt < 4; nt++) {
            int col = nBase + nt * 8 + c2;
            float2 bi = *(const float2*)(bias + col);
            #pragma unroll
            for (int mt = 0; mt < 2; mt++) {
                int g0 = row0 + mBase + mt * 16 + r0;
                float2 o0 = {acc[mt][nt][0] + bi.x, acc[mt][nt][1] + bi.y};
                *(float2*)(out + (size_t)g0 * DIM + col) = o0;
                float2 o1 = {acc[mt][nt][2] + bi.x, acc[mt][nt][3] + bi.y};
                *(float2*)(out + (size_t)(g0 + 8) * DIM + col) = o1;
            }
        }

        CP_WAIT0();
        __syncthreads();
        buf ^= 1;
    }
}

// ---------------- GATv2 aggregation: fixed-shift softmax, warp per node, 4-edge unroll ----------------
__device__ __forceinline__ float leaky_dot(float4 v, float4 x, float4 w) {
    float zx = v.x + x.x, zy = v.y + x.y, zz = v.z + x.z, zw = v.w + x.w;
    zx = fmaxf(zx, NEG_SLOPE * zx);   // leakyrelu: max(z, 0.2z)
    zy = fmaxf(zy, NEG_SLOPE * zy);
    zz = fmaxf(zz, NEG_SLOPE * zz);
    zw = fmaxf(zw, NEG_SLOPE * zw);
    return zx * w.x + zy * w.y + zz * w.z + zw * w.w;
}
__device__ __forceinline__ float hred8(float d) {
    d += __shfl_xor_sync(0xffffffffu, d, 1);
    d += __shfl_xor_sync(0xffffffffu, d, 2);
    d += __shfl_xor_sync(0xffffffffu, d, 4);
    return d;
}

__global__ __launch_bounds__(256) void k_gat(
    const float* __restrict__ xl, const float* __restrict__ xr,
    const float* __restrict__ att, const float* __restrict__ conv_bias,
    const float* __restrict__ bn_gamma, const float* __restrict__ bn_beta,
    const float* __restrict__ bn_mean, const float* __restrict__ bn_var,
    float* __restrict__ hout, int write_bf, int write_f32)
{
    int i = blockIdx.x * 8 + (threadIdx.x >> 5);
    if (i >= NODES) return;
    int lane = threadIdx.x & 31;
    int c = lane * 4;

    float4 w   = *(const float4*)(att + c);
    float4 xr4 = *(const float4*)(xr + (size_t)i * DIM + c);

    float4 xls = *(const float4*)(xl + (size_t)i * DIM + c);
    float m0 = hred8(leaky_dot(xls, xr4, w));
    float denom = 1.0f;
    float4 acc = xls;

    int beg = d_rowptr[i];
    int end = d_rowptr[i + 1];
    int j = beg;
    for (; j + 4 <= end; j += 4) {
        int s0 = d_srcs[j];
        int s1 = d_srcs[j + 1];
        int s2 = d_srcs[j + 2];
        int s3 = d_srcs[j + 3];
        float4 v0 = *(const float4*)(xl + (size_t)s0 * DIM + c);
        float4 v1 = *(const float4*)(xl + (size_t)s1 * DIM + c);
        float4 v2 = *(const float4*)(xl + (size_t)s2 * DIM + c);
        float4 v3 = *(const float4*)(xl + (size_t)s3 * DIM + c);
        float d0 = hred8(leaky_dot(v0, xr4, w));
        float d1 = hred8(leaky_dot(v1, xr4, w));
        float d2 = hred8(leaky_dot(v2, xr4, w));
        float d3 = hred8(leaky_dot(v3, xr4, w));
        float a0 = __expf(d0 - m0);
        float a1 = __expf(d1 - m0);
        float a2 = __expf(d2 - m0);
        float a3 = __expf(d3 - m0);
        denom += (a0 + a1) + (a2 + a3);
        acc.x += (a0 * v0.x + a1 * v1.x) + (a2 * v2.x + a3 * v3.x);
        acc.y += (a0 * v0.y + a1 * v1.y) + (a2 * v2.y + a3 * v3.y);
        acc.z += (a0 * v0.z + a1 * v1.z) + (a2 * v2.z + a3 * v3.z);
        acc.w += (a0 * v0.w + a1 * v1.w) + (a2 * v2.w + a3 * v3.w);
    }
    for (; j < end; j++) {
        int s0 = d_srcs[j];
        float4 v0 = *(const float4*)(xl + (size_t)s0 * DIM + c);
        float a0 = __expf(hred8(leaky_dot(v0, xr4, w)) - m0);
        denom += a0;
        acc.x += a0 * v0.x;
        acc.y += a0 * v0.y;
        acc.z += a0 * v0.z;
        acc.w += a0 * v0.w;
    }

    float inv = 1.0f / denom;
    float4 bias = *(const float4*)(conv_bias + c);
    float4 ga = *(const float4*)(bn_gamma + c);
    float4 be = *(const float4*)(bn_beta + c);
    float4 mu = *(const float4*)(bn_mean + c);
    float4 va = *(const float4*)(bn_var + c);
    float4 o;
    o.x = fmaxf((acc.x * inv + bias.x - mu.x) * rsqrtf(va.x + BN_EPS) * ga.x + be.x, 0.f);
    o.y = fmaxf((acc.y * inv + bias.y - mu.y) * rsqrtf(va.y + BN_EPS) * ga.y + be.y, 0.f);
    o.z = fmaxf((acc.z * inv + bias.z - mu.z) * rsqrtf(va.z + BN_EPS) * ga.z + be.z, 0.f);
    o.w = fmaxf((acc.w * inv + bias.w - mu.w) * rsqrtf(va.w + BN_EPS) * ga.w + be.w, 0.f);

    if (write_f32) *(float4*)(hout + (size_t)i * DIM + c) = o;
    if (write_bf) {
        __nv_bfloat16 hx = __float2bfloat16(o.x);
        __nv_bfloat16 hy = __float2bfloat16(o.y);
        __nv_bfloat16 hz = __float2bfloat16(o.z);
        __nv_bfloat16 hw = __float2bfloat16(o.w);
        __nv_bfloat162* ph = (__nv_bfloat162*)(d_hhi + (size_t)i * DIM + c);
        ph[0] = __nv_bfloat162(hx, hy);
        ph[1] = __nv_bfloat162(hz, hw);
        __nv_bfloat162* pl = (__nv_bfloat162*)(d_hlo + (size_t)i * DIM + c);
        pl[0] = __nv_bfloat162(__float2bfloat16(o.x - __bfloat162float(hx)),
                               __float2bfloat16(o.y - __bfloat162float(hy)));
        pl[1] = __nv_bfloat162(__float2bfloat16(o.z - __bfloat162float(hz)),
                               __float2bfloat16(o.w - __bfloat162float(hw)));
    }
}

// ---------------- mean pool (batch sorted) + MLP 128->64->2 ----------------
__global__ void k_pool_mlp(
    const float* __restrict__ h, const int* __restrict__ batch,
    const float* __restrict__ W1, const float* __restrict__ b1,
    const float* __restrict__ W2, const float* __restrict__ b2,
    float* __restrict__ out)
{
    __shared__ float p[DIM];
    __shared__ float hid[64];
    int g = blockIdx.x;
    int t = threadIdx.x;

    int lo = 0, hi = NODES;
    while (lo < hi) { int mid = (lo + hi) >> 1; if (batch[mid] < g) lo = mid + 1; else hi = mid; }
    int beg = lo;
    hi = NODES;
    while (lo < hi) { int mid = (lo + hi) >> 1; if (batch[mid] < g + 1) lo = mid + 1; else hi = mid; }
    int end = lo;

    float sum = 0.f;
    for (int n = beg; n < end; n++) sum += h[(size_t)n * DIM + t];
    float cnt = (float)(end - beg);
    p[t] = sum / fmaxf(cnt, 1.0f);
    __syncthreads();

    if (t < 64) {
        float a = b1[t];
        #pragma unroll 8
        for (int k = 0; k < DIM; k++) a = fmaf(p[k], W1[k * 64 + t], a);
        hid[t] = fmaxf(a, 0.f);
    }
    __syncthreads();

    if (t < 2) {
        float a = b2[t];
        #pragma unroll 8
        for (int k = 0; k < 64; k++) a = fmaf(hid[k], W2[k * 2 + t], a);
        out[g * 2 + t] = a;
    }
}

// ---------------- launch ----------------
extern "C" void kernel_launch(void* const* d_in, const int* in_sizes, int n_in,
                              void* d_out, int out_size)
{
    const float* x     = (const float*)d_in[0];
    const int*   ei    = (const int*)d_in[1];
    const int*   batch = (const int*)d_in[2];
    const float* Wl    = (const float*)d_in[3];
    const float* bl    = (const float*)d_in[4];
    const float* Wr    = (const float*)d_in[5];
    const float* br    = (const float*)d_in[6];
    const float* att   = (const float*)d_in[7];
    const float* cb    = (const float*)d_in[8];
    const float* bng   = (const float*)d_in[9];
    const float* bnb   = (const float*)d_in[10];
    const float* bnm   = (const float*)d_in[11];
    const float* bnv   = (const float*)d_in[12];
    const float* W1    = (const float*)d_in[13];
    const float* b1    = (const float*)d_in[14];
    const float* W2    = (const float*)d_in[15];
    const float* b2    = (const float*)d_in[16];
    float* out = (float*)d_out;

    float *h0, *xl, *xr;
    __nv_bfloat16 *hhi, *hlo, *whi, *wlo;
    cudaGetSymbolAddress((void**)&h0, d_h0);
    cudaGetSymbolAddress((void**)&xl, d_xl);
    cudaGetSymbolAddress((void**)&xr, d_xr);
    cudaGetSymbolAddress((void**)&hhi, d_hhi);
    cudaGetSymbolAddress((void**)&hlo, d_hlo);
    cudaGetSymbolAddress((void**)&whi, d_whi);
    cudaGetSymbolAddress((void**)&wlo, d_wlo);

    static int smem_set = 0;
    if (!smem_set) {
        cudaFuncSetAttribute(k_gemm_tc, cudaFuncAttributeMaxDynamicSharedMemorySize, GSMEM);
        smem_set = 1;
    }

    dim3 ggrid(74, 2);

    // order: launch #3 (ncu capture slot) = k_gemm_tc layer 0
    k_convx_zero<<<(NODES * DIM + 255) / 256, 256>>>(x);           // 0
    k_hist_cw<<<HIST_BLOCKS + 6, 256>>>(ei, Wl, Wr);               // 1
    k_scan<<<1, 1024>>>();                                         // 2
    k_gemm_tc<<<ggrid, 256, GSMEM>>>(hhi, hlo, whi, wlo, bl, br);  // 3  <-- profiled
    k_scatter<<<(EDGES + 255) / 256, 256>>>(ei);                   // 4

    for (int l = 0; l < 3; l++) {
        if (l > 0) {
            k_gemm_tc<<<ggrid, 256, GSMEM>>>(
                hhi, hlo,
                whi + (size_t)l * 2 * DIM * DIM, wlo + (size_t)l * 2 * DIM * DIM,
                bl + l * DIM, br + l * DIM);
        }
        k_gat<<<NODES / 8, 256>>>(xl, xr,
                                  att + l * DIM, cb + l * DIM,
                                  bng + l * DIM, bnb + l * DIM,
                                  bnm + l * DIM, bnv + l * DIM,
                                  h0, (l < 2) ? 1 : 0, (l == 2) ? 1 : 0);
    }

    k_pool_mlp<<<GRAPHS, 128>>>(h0, batch, W1, b1, W2, b2, out);
}